// round 3
// baseline (speedup 1.0000x reference)
#include <cuda_runtime.h>
#include <cstdint>

// ---------------------------------------------------------------------------
// LSTMRegressor: 2-layer LSTM (B=256,T=512,D=64,H=512) + FC(512)+ReLU + FC(8)
// Persistent-kernel design: 128 CTAs, one grid barrier per time tick.
// CTA b owns hidden columns [4b, 4b+4) of BOTH layers (layer1 lags 1 tick).
// ---------------------------------------------------------------------------

#define NB      128
#define THREADS 256
#define HPAD    68              // 64 + 4 pad (floats) -> conflict-free float4 LDS
#define HBUF    (256 * HPAD)    // one h-chunk buffer  (256 rows x 64 cols)
#define WBUF    (16 * 64)       // one w-chunk buffer  (16 gate cols x 64 k)
#define SMEM_FLOATS (2 * HBUF + 2 * WBUF)
#define SMEM_BYTES  (SMEM_FLOATS * 4)

// Persistent device state (scratch; allocation-free per harness rules)
__device__ float g_h0[2][256 * 512];
__device__ float g_h1[2][256 * 512];
__device__ unsigned g_bar_count;
__device__ unsigned g_bar_gen;

// ---------------------------------------------------------------------------
// helpers
// ---------------------------------------------------------------------------
__device__ __forceinline__ void cp16(float* sdst, const float* gsrc) {
    unsigned a = (unsigned)__cvta_generic_to_shared(sdst);
    asm volatile("cp.async.cg.shared.global [%0], [%1], 16;" :: "r"(a), "l"(gsrc));
}
__device__ __forceinline__ void cp_commit() { asm volatile("cp.async.commit_group;"); }
__device__ __forceinline__ void cp_wait0()  { asm volatile("cp.async.wait_group 0;"); }
__device__ __forceinline__ void cp_wait1()  { asm volatile("cp.async.wait_group 1;"); }

__device__ __forceinline__ float sigf(float x) {
    return __fdividef(1.0f, 1.0f + __expf(-x));
}
__device__ __forceinline__ float tanhfast(float x) {
    // 1 - 2/(e^{2x}+1); handles +/-inf saturation correctly
    return 1.0f - __fdividef(2.0f, __expf(2.0f * x) + 1.0f);
}

__device__ __forceinline__ void grid_barrier() {
    __threadfence();            // make this CTA's h-writes globally visible
    __syncthreads();
    if (threadIdx.x == 0) {
        unsigned gen = *((volatile unsigned*)&g_bar_gen);
        unsigned arrived = atomicAdd(&g_bar_count, 1u);
        if (arrived == NB - 1) {
            g_bar_count = 0;
            __threadfence();
            atomicAdd(&g_bar_gen, 1u);   // release
        } else {
            while (*((volatile unsigned*)&g_bar_gen) == gen) { __nanosleep(128); }
        }
    }
    __syncthreads();
}

// Issue async load of one 64-wide K chunk: h-block [256][64] + w-block [16][64]
__device__ __forceinline__ void issue_chunk(
    float* shh, float* shw,
    const float* __restrict__ src, long srcStride, int col0,
    const float* __restrict__ W, int Wld, int k0, int cta)
{
    const int tid  = threadIdx.x;
    const int row0 = tid >> 4;
    const int k4   = tid & 15;
    const float* s0 = src + col0 + k0 + (k4 << 2);
    float* d0 = shh + (k4 << 2);
    #pragma unroll
    for (int ii = 0; ii < 16; ++ii) {
        int row = row0 + (ii << 4);
        cp16(d0 + row * HPAD, s0 + (long)row * srcStride);
    }
    // weights: thread t loads gate-row (t>>4), float4 (t&15)
    {
        int c  = tid >> 4;
        int gc = ((c >> 2) << 9) + (cta << 2) + (c & 3);   // gate column in [0,2048)
        cp16(shw + c * 64 + (k4 << 2), W + (long)gc * Wld + k0 + (k4 << 2));
    }
    cp_commit();
}

__device__ __forceinline__ void compute_chunk(
    float acc[16], const float* shh, const float* shw, int r)
{
    #pragma unroll 2
    for (int k = 0; k < 64; k += 4) {
        float4 a = *(const float4*)&shh[r * HPAD + k];
        #pragma unroll
        for (int c = 0; c < 16; ++c) {
            float4 w = *(const float4*)&shw[c * 64 + k];
            acc[c] = fmaf(a.x, w.x, acc[c]);
            acc[c] = fmaf(a.y, w.y, acc[c]);
            acc[c] = fmaf(a.z, w.z, acc[c]);
            acc[c] = fmaf(a.w, w.w, acc[c]);
        }
    }
}

// acc[c] += sum_k src[row][col0+k] * W[gatecol(c)][k],  k in [0, ncols)
__device__ __forceinline__ void accum_part(
    float acc[16],
    const float* __restrict__ src, long srcStride, int col0, int ncols,
    const float* __restrict__ W, int Wld, int cta, int r,
    float* shh, float* shw)
{
    const int nchunk = ncols >> 6;
    issue_chunk(shh, shw, src, srcStride, col0, W, Wld, 0, cta);
    for (int ci = 0; ci < nchunk; ++ci) {
        float* curh = shh + (ci & 1) * HBUF;
        float* curw = shw + (ci & 1) * WBUF;
        if (ci + 1 < nchunk) {
            issue_chunk(shh + ((ci + 1) & 1) * HBUF, shw + ((ci + 1) & 1) * WBUF,
                        src, srcStride, col0, W, Wld, (ci + 1) << 6, cta);
            cp_wait1();
        } else {
            cp_wait0();
        }
        __syncthreads();
        compute_chunk(acc, curh, curw, r);
        __syncthreads();
    }
}

__device__ __forceinline__ void cell_update(
    const float acc[16], const float bias[16], float cst[4],
    float* __restrict__ hout, int r, int cta)
{
    #pragma unroll
    for (int j = 0; j < 4; ++j) {
        float ig = sigf(acc[j]        + bias[j]);
        float fg = sigf(acc[4 + j]    + bias[4 + j]);
        float gg = tanhfast(acc[8 + j]  + bias[8 + j]);
        float og = sigf(acc[12 + j]   + bias[12 + j]);
        float cc = fmaf(fg, cst[j], ig * gg);
        cst[j] = cc;
        float h = og * tanhfast(cc);
        __stcg(hout + r * 512 + (cta << 2) + j, h);
    }
}

// ---------------------------------------------------------------------------
// main persistent kernel
// ---------------------------------------------------------------------------
__global__ void __launch_bounds__(THREADS, 1) lstm_kernel(
    const float* __restrict__ x,
    const float* __restrict__ Wih0, const float* __restrict__ Whh0,
    const float* __restrict__ bi0,  const float* __restrict__ bh0,
    const float* __restrict__ Wih1, const float* __restrict__ Whh1,
    const float* __restrict__ bi1,  const float* __restrict__ bh1,
    const float* __restrict__ Wfc1, const float* __restrict__ bfc1,
    const float* __restrict__ Wfc2, const float* __restrict__ bfc2,
    float* __restrict__ out)
{
    extern __shared__ float smem[];
    float* shh = smem;                 // 2 * HBUF
    float* shw = smem + 2 * HBUF;      // 2 * WBUF

    const int r   = threadIdx.x;       // batch row handled by this thread
    const int cta = blockIdx.x;        // hidden-column group [4*cta, 4*cta+4)

    // hoist biases (b_ih + b_hh) for both layers into registers
    float bias0[16], bias1[16];
    #pragma unroll
    for (int c = 0; c < 16; ++c) {
        int gc = ((c >> 2) << 9) + (cta << 2) + (c & 3);
        bias0[c] = bi0[gc] + bh0[gc];
        bias1[c] = bi1[gc] + bh1[gc];
    }

    float c0[4] = {0.f, 0.f, 0.f, 0.f};
    float c1[4] = {0.f, 0.f, 0.f, 0.f};

    // tick t: layer0 processes step t (t<512); layer1 processes step t-1 (t>=1)
    for (int t = 0; t <= 512; ++t) {
        if (t < 512) {
            float acc[16];
            #pragma unroll
            for (int c = 0; c < 16; ++c) acc[c] = 0.f;
            // x contribution: x[b][t][0:64]
            accum_part(acc, x, (long)512 * 64, t * 64, 64, Wih0, 64, cta, r, shh, shw);
            // recurrent contribution
            if (t > 0)
                accum_part(acc, g_h0[(t - 1) & 1], 512, 0, 512, Whh0, 512, cta, r, shh, shw);
            cell_update(acc, bias0, c0, g_h0[t & 1], r, cta);
        }
        if (t >= 1) {
            const int s = t - 1;
            float acc[16];
            #pragma unroll
            for (int c = 0; c < 16; ++c) acc[c] = 0.f;
            // input contribution from layer0 output at step s
            accum_part(acc, g_h0[s & 1], 512, 0, 512, Wih1, 512, cta, r, shh, shw);
            // recurrent contribution
            if (s > 0)
                accum_part(acc, g_h1[(s - 1) & 1], 512, 0, 512, Whh1, 512, cta, r, shh, shw);
            cell_update(acc, bias1, c1, g_h1[s & 1], r, cta);
        }
        grid_barrier();
    }

    // -----------------------------------------------------------------------
    // FC head: rows [2*cta, 2*cta+2) of h1[:, 511, :]  (parity 511&1 == 1)
    // -----------------------------------------------------------------------
    const float* hlast = g_h1[1];
    const int r0 = 2 * cta;
    float* shA = smem;            // [2][512] last hidden rows
    float* shZ = smem + 1024;     // [2][512] relu(fc1)

    for (int i = threadIdx.x; i < 1024; i += THREADS) {
        int row = i >> 9, k = i & 511;
        shA[i] = __ldcg(hlast + (long)(r0 + row) * 512 + k);
    }
    __syncthreads();

    #pragma unroll
    for (int ii = 0; ii < 2; ++ii) {
        int cc = threadIdx.x + THREADS * ii;      // fc1 output column
        float a0 = bfc1[cc];
        float a1 = a0;
        const float4* wr  = (const float4*)(Wfc1 + (long)cc * 512);
        const float4* hv0 = (const float4*)shA;
        const float4* hv1 = (const float4*)(shA + 512);
        #pragma unroll 4
        for (int k4 = 0; k4 < 128; ++k4) {
            float4 w = wr[k4];
            float4 p = hv0[k4];
            float4 q = hv1[k4];
            a0 = fmaf(w.x, p.x, a0); a0 = fmaf(w.y, p.y, a0);
            a0 = fmaf(w.z, p.z, a0); a0 = fmaf(w.w, p.w, a0);
            a1 = fmaf(w.x, q.x, a1); a1 = fmaf(w.y, q.y, a1);
            a1 = fmaf(w.z, q.z, a1); a1 = fmaf(w.w, q.w, a1);
        }
        shZ[cc]       = fmaxf(a0, 0.f);
        shZ[512 + cc] = fmaxf(a1, 0.f);
    }
    __syncthreads();

    // fc2: 8 warps, warp w computes output column w for both rows
    const int wpid = threadIdx.x >> 5;
    const int lane = threadIdx.x & 31;
    #pragma unroll
    for (int row = 0; row < 2; ++row) {
        const float4* zz = (const float4*)(shZ + row * 512);
        const float4* wf = (const float4*)(Wfc2 + (long)wpid * 512);
        float s = 0.f;
        #pragma unroll
        for (int k4 = lane; k4 < 128; k4 += 32) {
            float4 ww = wf[k4];
            float4 zv = zz[k4];
            s = fmaf(ww.x, zv.x, s); s = fmaf(ww.y, zv.y, s);
            s = fmaf(ww.z, zv.z, s); s = fmaf(ww.w, zv.w, s);
        }
        #pragma unroll
        for (int off = 16; off; off >>= 1) s += __shfl_xor_sync(0xFFFFFFFFu, s, off);
        if (lane == 0) out[(r0 + row) * 8 + wpid] = s + bfc2[wpid];
    }
}

// ---------------------------------------------------------------------------
// launch
// ---------------------------------------------------------------------------
extern "C" void kernel_launch(void* const* d_in, const int* in_sizes, int n_in,
                              void* d_out, int out_size)
{
    const float* x    = (const float*)d_in[0];
    const float* Wih0 = (const float*)d_in[1];
    const float* Whh0 = (const float*)d_in[2];
    const float* bi0  = (const float*)d_in[3];
    const float* bh0  = (const float*)d_in[4];
    const float* Wih1 = (const float*)d_in[5];
    const float* Whh1 = (const float*)d_in[6];
    const float* bi1  = (const float*)d_in[7];
    const float* bh1  = (const float*)d_in[8];
    const float* Wfc1 = (const float*)d_in[9];
    const float* bfc1 = (const float*)d_in[10];
    const float* Wfc2 = (const float*)d_in[11];
    const float* bfc2 = (const float*)d_in[12];
    float* out = (float*)d_out;

    cudaFuncSetAttribute(lstm_kernel, cudaFuncAttributeMaxDynamicSharedMemorySize,
                         SMEM_BYTES);

    lstm_kernel<<<NB, THREADS, SMEM_BYTES>>>(
        x, Wih0, Whh0, bi0, bh0, Wih1, Whh1, bi1, bh1,
        Wfc1, bfc1, Wfc2, bfc2, out);
}

// round 4
// speedup vs baseline: 7.3355x; 7.3355x over previous
#include <cuda_runtime.h>
#include <cuda_fp16.h>
#include <cstdint>

// ---------------------------------------------------------------------------
// LSTMRegressor (B=256,T=512,D=64,H=512) x2 + FC512/ReLU + FC8
// Tensor-core persistent kernel: 128 CTAs x 256 thr, mma.m16n8k16 f16->f32.
// ---------------------------------------------------------------------------
#define NB       128
#define THREADS  256
#define NSTAGE   4
#define CHUNK_B  32768u          // staged tile: 256 rows x 128B (64 fp16)
#define WTILE_B  2048            // weight tile: 16 rows x 128B
#define NWCHUNK  25

#define MBAR_OFF  0              // FULL[4]@0, EMPTY[4]@32
#define WS_OFF    1024
#define HS_OFF    52224          // 1024 + 25*2048, 128B aligned
#define SMEM_BYTES (HS_OFF + NSTAGE * (int)CHUNK_B)

__device__ __align__(128) __half g_x16[512][256 * 64];
__device__ __align__(128) __half g_h0[2][8][256 * 64];
__device__ __align__(128) __half g_h1[2][8][256 * 64];
__device__ float g_hlast[256 * 512];
__device__ unsigned g_bar_count;
__device__ unsigned g_bar_gen;

// ---------------------------------------------------------------------------
__device__ __forceinline__ uint32_t smem_u32(const void* p) {
    uint32_t a;
    asm("{ .reg .u64 t; cvta.to.shared.u64 t, %1; cvt.u32.u64 %0, t; }"
        : "=r"(a) : "l"(p));
    return a;
}
__device__ __forceinline__ float sigf(float x) {
    return __fdividef(1.0f, 1.0f + __expf(-x));
}
__device__ __forceinline__ float tanhfast(float x) {
    return 1.0f - __fdividef(2.0f, __expf(2.0f * x) + 1.0f);
}
__device__ __forceinline__ uint32_t swz(uint32_t off) {
    return off ^ ((off >> 3) & 0x70u);
}
__device__ __forceinline__ void mbar_init(uint32_t a, unsigned c) {
    asm volatile("mbarrier.init.shared.b64 [%0], %1;" :: "r"(a), "r"(c) : "memory");
}
__device__ __forceinline__ void mbar_arrive(uint32_t a) {
    asm volatile("mbarrier.arrive.shared.b64 _, [%0];" :: "r"(a) : "memory");
}
__device__ __forceinline__ void mbar_wait(uint32_t a, unsigned par) {
    asm volatile(
        "{\n\t.reg .pred P;\n"
        "W%=:\n\tmbarrier.try_wait.parity.acquire.cta.shared::cta.b64 P, [%0], %1;\n"
        "\t@P bra E%=;\n\tbra W%=;\nE%=:\n\t}"
        :: "r"(a), "r"(par) : "memory");
}
__device__ __forceinline__ void stg32(void* p, uint32_t v) {
    asm volatile("st.global.cg.b32 [%0], %1;" :: "l"(p), "r"(v) : "memory");
}
__device__ __forceinline__ void stgf(float* p, float v) {
    asm volatile("st.global.cg.f32 [%0], %1;" :: "l"(p), "f"(v) : "memory");
}
__device__ __forceinline__ void issue_chunk(uint32_t FULL, uint32_t EMPTY,
                                            uint32_t HSB, unsigned gid,
                                            const void* src) {
    const uint32_t st = gid & 3u;
    const unsigned ph = (gid >> 2) & 1u;
    mbar_wait(EMPTY + st * 8, ph ^ 1u);
    asm volatile("mbarrier.arrive.expect_tx.shared.b64 _, [%0], %1;"
                 :: "r"(FULL + st * 8), "r"(CHUNK_B) : "memory");
    asm volatile(
        "cp.async.bulk.shared::cluster.global.mbarrier::complete_tx::bytes "
        "[%0], [%1], %2, [%3];"
        :: "r"(HSB + st * CHUNK_B), "l"(src), "r"(CHUNK_B), "r"(FULL + st * 8)
        : "memory");
}
__device__ __forceinline__ void ldmA(uint32_t a[4], uint32_t addr) {
    asm volatile("ldmatrix.sync.aligned.m8n8.x4.shared.b16 {%0,%1,%2,%3}, [%4];"
                 : "=r"(a[0]), "=r"(a[1]), "=r"(a[2]), "=r"(a[3]) : "r"(addr));
}
__device__ __forceinline__ void ldmB(uint32_t b[2], uint32_t addr) {
    asm volatile("ldmatrix.sync.aligned.m8n8.x2.shared.b16 {%0,%1}, [%2];"
                 : "=r"(b[0]), "=r"(b[1]) : "r"(addr));
}
__device__ __forceinline__ void mma16816(float d[4], const uint32_t a[4],
                                         const uint32_t b[2]) {
    asm volatile(
        "mma.sync.aligned.m16n8k16.row.col.f32.f16.f16.f32 "
        "{%0,%1,%2,%3}, {%4,%5,%6,%7}, {%8,%9}, {%0,%1,%2,%3};"
        : "+f"(d[0]), "+f"(d[1]), "+f"(d[2]), "+f"(d[3])
        : "r"(a[0]), "r"(a[1]), "r"(a[2]), "r"(a[3]), "r"(b[0]), "r"(b[1]));
}
__device__ __forceinline__ void grid_barrier() {
    __threadfence();
    __syncthreads();
    if (threadIdx.x == 0) {
        unsigned gen = *((volatile unsigned*)&g_bar_gen);
        unsigned arrived = atomicAdd(&g_bar_count, 1u);
        if (arrived == NB - 1) {
            g_bar_count = 0;
            __threadfence();
            atomicAdd(&g_bar_gen, 1u);
        } else {
            while (*((volatile unsigned*)&g_bar_gen) == gen) { __nanosleep(64); }
            __threadfence();
        }
    }
    __syncthreads();
}

// One K=64 chunk: accX += A(256x64 staged) * Wtile^T, up to two weight tiles.
__device__ __forceinline__ void gemm_chunk(
    float accA[2][2][4], float accB[2][2][4],
    uint32_t hsaddr, uint32_t wsb, int w0, int w1,
    bool dA, bool dB, int wid, int lane)
{
    const int rn   = lane & 7;
    const int subB = (lane >> 3) & 1;
    const int subm = (lane >> 3) & 1;
    const int subk = lane >> 4;
    #pragma unroll
    for (int ks = 0; ks < 4; ++ks) {
        uint32_t bA[2][2], bB[2][2];
        const int kelB = ks * 16 + (subB << 3);
        if (dA) {
            #pragma unroll
            for (int nt = 0; nt < 2; ++nt)
                ldmB(bA[nt], wsb + w0 * WTILE_B +
                     swz((uint32_t)(nt * 8 + rn) * 128 + kelB * 2));
        }
        if (dB) {
            #pragma unroll
            for (int nt = 0; nt < 2; ++nt)
                ldmB(bB[nt], wsb + w1 * WTILE_B +
                     swz((uint32_t)(nt * 8 + rn) * 128 + kelB * 2));
        }
        #pragma unroll
        for (int mt = 0; mt < 2; ++mt) {
            const int r    = (2 * wid + mt) * 16 + (subm << 3) + rn;
            const int kelA = ks * 16 + (subk << 3);
            uint32_t a[4];
            ldmA(a, hsaddr + swz((uint32_t)r * 128 + kelA * 2));
            if (dA) { mma16816(accA[mt][0], a, bA[0]); mma16816(accA[mt][1], a, bA[1]); }
            if (dB) { mma16816(accB[mt][0], a, bB[0]); mma16816(accB[mt][1], a, bB[1]); }
        }
    }
}

__device__ __forceinline__ void cell_update(
    float acc[2][2][4], float cst[2][2][2], char* ghbase, float* hlast,
    int cta, int wid, int lane)
{
    const int q = lane & 3;
    #pragma unroll
    for (int mt = 0; mt < 2; ++mt) {
        float fA[4], oA[4];
        #pragma unroll
        for (int rdx = 0; rdx < 4; ++rdx) {
            fA[rdx] = __shfl_xor_sync(0xFFFFFFFFu, acc[mt][0][rdx], 2);
            oA[rdx] = __shfl_xor_sync(0xFFFFFFFFu, acc[mt][1][rdx], 2);
        }
        if (q < 2) {
            #pragma unroll
            for (int rh = 0; rh < 2; ++rh) {
                float hv[2];
                #pragma unroll
                for (int e = 0; e < 2; ++e) {
                    const int rdx = rh * 2 + e;
                    float ig = sigf(acc[mt][0][rdx]);
                    float gg = tanhfast(acc[mt][1][rdx]);
                    float fg = sigf(fA[rdx]);
                    float og = sigf(oA[rdx]);
                    float cc = fmaf(fg, cst[mt][rh][e], ig * gg);
                    cst[mt][rh][e] = cc;
                    hv[e] = og * tanhfast(cc);
                }
                const int b    = (2 * wid + mt) * 16 + (lane >> 2) + rh * 8;
                const int khid = 4 * cta + 2 * q;
                const int kc   = khid >> 6, kel = khid & 63;
                __half2 h2 = __floats2half2_rn(hv[0], hv[1]);
                stg32(ghbase + (size_t)kc * CHUNK_B +
                      swz((uint32_t)b * 128 + kel * 2),
                      *(uint32_t*)&h2);
                if (hlast) {
                    stgf(hlast + b * 512 + khid,     hv[0]);
                    stgf(hlast + b * 512 + khid + 1, hv[1]);
                }
            }
        }
    }
}

__device__ __forceinline__ const char* chunk_src(
    int i, bool doL0, bool h0grp,
    const char* xsrc, const char* h0src, const char* h1src)
{
    if (doL0)  { if (i == 0) return xsrc; --i; }
    if (h0grp) { if (i < 8)  return h0src + (size_t)i * CHUNK_B; i -= 8; }
    return h1src + (size_t)i * CHUNK_B;
}

// ---------------------------------------------------------------------------
__global__ void __launch_bounds__(THREADS, 1) lstm_mma_kernel(
    const float* __restrict__ x,
    const float* __restrict__ Wih0, const float* __restrict__ Whh0,
    const float* __restrict__ bi0,  const float* __restrict__ bh0,
    const float* __restrict__ Wih1, const float* __restrict__ Whh1,
    const float* __restrict__ bi1,  const float* __restrict__ bh1,
    const float* __restrict__ Wfc1, const float* __restrict__ bfc1,
    const float* __restrict__ Wfc2, const float* __restrict__ bfc2,
    float* __restrict__ out)
{
    extern __shared__ char smem[];
    const uint32_t sbase = smem_u32(smem);
    const uint32_t FULL  = sbase + MBAR_OFF;
    const uint32_t EMPTY = sbase + MBAR_OFF + 32;
    const uint32_t WSB   = sbase + WS_OFF;
    const uint32_t HSB   = sbase + HS_OFF;

    const int tid  = threadIdx.x;
    const int lane = tid & 31;
    const int wid  = tid >> 5;
    const int cta  = blockIdx.x;

    if (tid == 0) {
        #pragma unroll
        for (int s = 0; s < NSTAGE; ++s) {
            mbar_init(FULL + s * 8, 1);
            mbar_init(EMPTY + s * 8, 8);
        }
    }

    // weights -> resident fp16 SW128 tiles
    for (int idx = tid; idx < NWCHUNK * 16; idx += THREADS) {
        const int ch = idx >> 4, n = idx & 15;
        const float* Wsrc; int ld, k0;
        if (ch == 0)      { Wsrc = Wih0; ld = 64;  k0 = 0; }
        else if (ch < 9)  { Wsrc = Whh0; ld = 512; k0 = (ch - 1) * 64; }
        else if (ch < 17) { Wsrc = Wih1; ld = 512; k0 = (ch - 9) * 64; }
        else              { Wsrc = Whh1; ld = 512; k0 = (ch - 17) * 64; }
        const int gc = (n >> 2) * 512 + cta * 4 + (n & 3);
        const float* src = Wsrc + (long)gc * ld + k0;
        char* tb = smem + WS_OFF + ch * WTILE_B;
        for (int k = 0; k < 64; k += 2) {
            __half2 v = __floats2half2_rn(src[k], src[k + 1]);
            *(__half2*)(tb + swz((uint32_t)n * 128 + k * 2)) = v;
        }
    }

    // biases for this lane's accumulator columns
    const int q = lane & 3;
    float bias0[2][2], bias1[2][2];
    #pragma unroll
    for (int nt = 0; nt < 2; ++nt)
        #pragma unroll
        for (int e = 0; e < 2; ++e) {
            const int c  = nt * 8 + q * 2 + e;
            const int gc = (c >> 2) * 512 + cta * 4 + (c & 3);
            bias0[nt][e] = bi0[gc] + bh0[gc];
            bias1[nt][e] = bi1[gc] + bh1[gc];
        }

    // x -> fp16 swizzled tiles (this CTA: 4 time steps; thread = batch row)
    for (int tt = 0; tt < 4; ++tt) {
        const int t = cta * 4 + tt;
        const float* xr = x + ((long)tid * 512 + t) * 64;
        char* dst = (char*)g_x16 + (size_t)t * CHUNK_B;
        for (int k = 0; k < 64; k += 2) {
            __half2 v = __floats2half2_rn(xr[k], xr[k + 1]);
            *(__half2*)(dst + swz((uint32_t)tid * 128 + k * 2)) = v;
        }
    }
    asm volatile("fence.proxy.async.global;" ::: "memory");
    grid_barrier();

    float cst0[2][2][2] = {}, cst1[2][2][2] = {};
    unsigned cons = 0;

    for (int t = 0; t <= 512; ++t) {
        const bool doL0  = (t < 512);
        const bool rec0  = doL0 && (t > 0);
        const bool doL1  = (t >= 1);
        const bool rec1  = (t >= 2);
        const bool h0grp = rec0 || doL1;
        const int  nch   = (doL0 ? 1 : 0) + (h0grp ? 8 : 0) + (rec1 ? 8 : 0);

        const char* xsrc  = (const char*)g_x16 + (size_t)t * CHUNK_B;
        const char* h0src = (const char*)g_h0[(t - 1) & 1];
        const char* h1src = (const char*)g_h1[t & 1];

        const unsigned gc0 = cons;
        int pi = nch < NSTAGE ? nch : NSTAGE;
        if (tid == 0)
            for (int i2 = 0; i2 < pi; ++i2)
                issue_chunk(FULL, EMPTY, HSB, gc0 + i2,
                            chunk_src(i2, doL0, h0grp, xsrc, h0src, h1src));

        float acc0[2][2][4], acc1[2][2][4];
        #pragma unroll
        for (int mt = 0; mt < 2; ++mt)
            #pragma unroll
            for (int nt = 0; nt < 2; ++nt) {
                acc0[mt][nt][0] = bias0[nt][0]; acc0[mt][nt][1] = bias0[nt][1];
                acc0[mt][nt][2] = bias0[nt][0]; acc0[mt][nt][3] = bias0[nt][1];
                acc1[mt][nt][0] = bias1[nt][0]; acc1[mt][nt][1] = bias1[nt][1];
                acc1[mt][nt][2] = bias1[nt][0]; acc1[mt][nt][3] = bias1[nt][1];
            }

        #define CONSUME_PRE() mbar_wait(FULL + (cons & 3) * 8, (cons >> 2) & 1)
        #define CONSUME_POST()                                               \
            do {                                                             \
                if (lane == 0) mbar_arrive(EMPTY + (cons & 3) * 8);          \
                ++cons;                                                      \
                if (pi < nch) {                                              \
                    if (tid == 0)                                            \
                        issue_chunk(FULL, EMPTY, HSB, gc0 + pi,              \
                                    chunk_src(pi, doL0, h0grp,               \
                                              xsrc, h0src, h1src));          \
                    ++pi;                                                    \
                }                                                            \
            } while (0)

        if (doL0) {
            CONSUME_PRE();
            gemm_chunk(acc0, acc1, HSB + (cons & 3) * CHUNK_B, WSB,
                       0, 0, true, false, wid, lane);
            CONSUME_POST();
        }
        if (h0grp) {
            for (int j = 0; j < 8; ++j) {
                CONSUME_PRE();
                gemm_chunk(acc0, acc1, HSB + (cons & 3) * CHUNK_B, WSB,
                           1 + j, 9 + j, rec0, doL1, wid, lane);
                CONSUME_POST();
            }
        }
        if (doL0)
            cell_update(acc0, cst0, (char*)g_h0[t & 1], nullptr, cta, wid, lane);
        if (rec1) {
            for (int j = 0; j < 8; ++j) {
                CONSUME_PRE();
                gemm_chunk(acc1, acc0, HSB + (cons & 3) * CHUNK_B, WSB,
                           17 + j, 0, true, false, wid, lane);
                CONSUME_POST();
            }
        }
        if (doL1)
            cell_update(acc1, cst1, (char*)g_h1[(t - 1) & 1],
                        (t - 1) == 511 ? g_hlast : nullptr, cta, wid, lane);

        asm volatile("fence.proxy.async.global;" ::: "memory");
        grid_barrier();
    }

    // ---------------- FC head: rows [2*cta, 2*cta+2) ----------------
    float* sm  = (float*)smem;
    float* shA = sm;
    float* shZ = sm + 1024;
    const int r0 = 2 * cta;
    for (int i = tid; i < 1024; i += THREADS) {
        int row = i >> 9, k = i & 511;
        shA[i] = __ldcg(g_hlast + (long)(r0 + row) * 512 + k);
    }
    __syncthreads();

    #pragma unroll
    for (int ii = 0; ii < 2; ++ii) {
        int cc = tid + THREADS * ii;
        float a0 = bfc1[cc];
        float a1 = a0;
        const float4* wr  = (const float4*)(Wfc1 + (long)cc * 512);
        const float4* hv0 = (const float4*)shA;
        const float4* hv1 = (const float4*)(shA + 512);
        #pragma unroll 4
        for (int k4 = 0; k4 < 128; ++k4) {
            float4 w = wr[k4];
            float4 p = hv0[k4];
            float4 qv = hv1[k4];
            a0 = fmaf(w.x, p.x, a0);  a0 = fmaf(w.y, p.y, a0);
            a0 = fmaf(w.z, p.z, a0);  a0 = fmaf(w.w, p.w, a0);
            a1 = fmaf(w.x, qv.x, a1); a1 = fmaf(w.y, qv.y, a1);
            a1 = fmaf(w.z, qv.z, a1); a1 = fmaf(w.w, qv.w, a1);
        }
        shZ[cc]       = fmaxf(a0, 0.f);
        shZ[512 + cc] = fmaxf(a1, 0.f);
    }
    __syncthreads();

    #pragma unroll
    for (int row = 0; row < 2; ++row) {
        const float4* zz = (const float4*)(shZ + row * 512);
        const float4* wf = (const float4*)(Wfc2 + (long)wid * 512);
        float s = 0.f;
        #pragma unroll
        for (int k4 = lane; k4 < 128; k4 += 32) {
            float4 ww = wf[k4];
            float4 zv = zz[k4];
            s = fmaf(ww.x, zv.x, s); s = fmaf(ww.y, zv.y, s);
            s = fmaf(ww.z, zv.z, s); s = fmaf(ww.w, zv.w, s);
        }
        #pragma unroll
        for (int off = 16; off; off >>= 1) s += __shfl_xor_sync(0xFFFFFFFFu, s, off);
        if (lane == 0) out[(r0 + row) * 8 + wid] = s + bfc2[wid];
    }
}

// ---------------------------------------------------------------------------
extern "C" void kernel_launch(void* const* d_in, const int* in_sizes, int n_in,
                              void* d_out, int out_size)
{
    const float* x    = (const float*)d_in[0];
    const float* Wih0 = (const float*)d_in[1];
    const float* Whh0 = (const float*)d_in[2];
    const float* bi0  = (const float*)d_in[3];
    const float* bh0  = (const float*)d_in[4];
    const float* Wih1 = (const float*)d_in[5];
    const float* Whh1 = (const float*)d_in[6];
    const float* bi1  = (const float*)d_in[7];
    const float* bh1  = (const float*)d_in[8];
    const float* Wfc1 = (const float*)d_in[9];
    const float* bfc1 = (const float*)d_in[10];
    const float* Wfc2 = (const float*)d_in[11];
    const float* bfc2 = (const float*)d_in[12];
    float* out = (float*)d_out;

    cudaFuncSetAttribute(lstm_mma_kernel,
                         cudaFuncAttributeMaxDynamicSharedMemorySize, SMEM_BYTES);
    lstm_mma_kernel<<<NB, THREADS, SMEM_BYTES>>>(
        x, Wih0, Whh0, bi0, bh0, Wih1, Whh1, bi1, bh1,
        Wfc1, bfc1, Wfc2, bfc2, out);
}

// round 6
// speedup vs baseline: 9.4582x; 1.2894x over previous
#include <cuda_runtime.h>
#include <cuda_fp16.h>
#include <cstdint>

// ---------------------------------------------------------------------------
// LSTMRegressor (B=256,T=512,D=64,H=512) x2 + FC512/ReLU + FC8
// R4: M-split (2 x 64 grid) + 2-CTA cluster TMA multicast.
//   CTA (mh, ngrp): rows [mh*128,+128), hidden units [ngrp*8,+8) both layers.
//   Cluster pair = same mh, adjacent ngrp -> identical chunk reads, multicast.
//   Chunks K=128 (32KB), 3-stage mbarrier ring, ldmatrix.x4 + mma.m16n8k16.
//   Gate layout i|f|g|o = 4 n-tiles -> shuffle-free cell update.
// ---------------------------------------------------------------------------
#define NB       128
#define THREADS  256
#define NSTAGE   3
#define STAGE_B  32768u
#define WTILE_B  4096
#define WS_OFF   1024
#define HS_OFF   (WS_OFF + 25 * WTILE_B)            // 103424 (1KB aligned)
#define SMEM_BYTES (HS_OFF + NSTAGE * (int)STAGE_B) // 201728

__device__ __align__(128) __half g_x16[512 * 2 * 8192];      // [t][mh][16KB tile]
__device__ __align__(128) __half g_h0[2][2 * 4 * 2 * 8192];  // [par][mh][kc][kh][16KB]
__device__ __align__(128) __half g_h1[2][2 * 4 * 2 * 8192];
__device__ float g_hlast[256 * 512];
__device__ unsigned g_bar_count;
__device__ unsigned g_bar_gen;

// ---------------------------------------------------------------------------
__device__ __forceinline__ uint32_t smem_u32(const void* p) {
    uint32_t a;
    asm("{ .reg .u64 t; cvta.to.shared.u64 t, %1; cvt.u32.u64 %0, t; }"
        : "=r"(a) : "l"(p));
    return a;
}
__device__ __forceinline__ float sigf(float x) {
    return __fdividef(1.0f, 1.0f + __expf(-x));
}
__device__ __forceinline__ float tanhfast(float x) {
    return 1.0f - __fdividef(2.0f, __expf(2.0f * x) + 1.0f);
}
__device__ __forceinline__ uint32_t swz(uint32_t off) {
    return off ^ ((off >> 3) & 0x70u);
}
__device__ __forceinline__ void mbar_init(uint32_t a, unsigned c) {
    asm volatile("mbarrier.init.shared.b64 [%0], %1;" :: "r"(a), "r"(c) : "memory");
}
__device__ __forceinline__ void mbar_arrive(uint32_t a) {
    asm volatile("mbarrier.arrive.shared.b64 _, [%0];" :: "r"(a) : "memory");
}
__device__ __forceinline__ void mbar_arrive_remote(uint32_t a) {
    asm volatile("mbarrier.arrive.shared::cluster.b64 _, [%0];" :: "r"(a) : "memory");
}
__device__ __forceinline__ void mbar_wait(uint32_t a, unsigned par) {
    asm volatile(
        "{\n\t.reg .pred P;\n"
        "W%=:\n\tmbarrier.try_wait.parity.acquire.cta.shared::cta.b64 P, [%0], %1;\n"
        "\t@P bra E%=;\n\tbra W%=;\nE%=:\n\t}"
        :: "r"(a), "r"(par) : "memory");
}
__device__ __forceinline__ void stg32(void* p, uint32_t v) {
    asm volatile("st.global.cg.b32 [%0], %1;" :: "l"(p), "r"(v) : "memory");
}
__device__ __forceinline__ void stgf(float* p, float v) {
    asm volatile("st.global.cg.f32 [%0], %1;" :: "l"(p), "f"(v) : "memory");
}
__device__ __forceinline__ void ldm4(uint32_t r[4], uint32_t addr) {
    asm volatile("ldmatrix.sync.aligned.m8n8.x4.shared.b16 {%0,%1,%2,%3}, [%4];"
                 : "=r"(r[0]), "=r"(r[1]), "=r"(r[2]), "=r"(r[3]) : "r"(addr));
}
__device__ __forceinline__ void mma16816(float d[4], const uint32_t a[4],
                                         const uint32_t b[2]) {
    asm volatile(
        "mma.sync.aligned.m16n8k16.row.col.f32.f16.f16.f32 "
        "{%0,%1,%2,%3}, {%4,%5,%6,%7}, {%8,%9}, {%0,%1,%2,%3};"
        : "+f"(d[0]), "+f"(d[1]), "+f"(d[2]), "+f"(d[3])
        : "r"(a[0]), "r"(a[1]), "r"(a[2]), "r"(a[3]), "r"(b[0]), "r"(b[1]));
}
__device__ __forceinline__ void grid_barrier() {
    __threadfence();
    __syncthreads();
    if (threadIdx.x == 0) {
        unsigned gen = *((volatile unsigned*)&g_bar_gen);
        unsigned arrived = atomicAdd(&g_bar_count, 1u);
        if (arrived == NB - 1) {
            g_bar_count = 0;
            __threadfence();
            atomicAdd(&g_bar_gen, 1u);
        } else {
            while (*((volatile unsigned*)&g_bar_gen) == gen) { __nanosleep(64); }
            __threadfence();
        }
    }
    __syncthreads();
}

// Producer side for one chunk: both CTAs expect_tx; issuer (gid parity) copies.
__device__ __forceinline__ void issue_one(uint32_t FULL, uint32_t EMPTY,
                                          uint32_t HSB, unsigned gid,
                                          const void* src, uint32_t bytes,
                                          int rank) {
    const uint32_t st = gid % 3u;
    const unsigned ph = (gid / 3u) & 1u;
    mbar_wait(EMPTY + st * 8, ph ^ 1u);
    asm volatile("mbarrier.arrive.expect_tx.shared.b64 _, [%0], %1;"
                 :: "r"(FULL + st * 8), "r"(bytes) : "memory");
    if ((int)(gid & 1u) == rank)
        asm volatile(
            "cp.async.bulk.shared::cluster.global.mbarrier::complete_tx::bytes"
            ".multicast::cluster [%0], [%1], %2, [%3], %4;"
            :: "r"(HSB + st * STAGE_B), "l"(src), "r"(bytes),
               "r"(FULL + st * 8), "h"((unsigned short)0x3)
            : "memory");
}

// One staged chunk (nkh k-halves of 64): acc{0,1}[nt] += A(128 x 64kh) * W^T.
__device__ __forceinline__ void gemm_chunk(
    float a0[4][4], float a1[4][4],
    uint32_t sa, uint32_t w0k, uint32_t w1k,
    bool d0, bool d1, int nkh, int wid, int lane)
{
    const int rn = lane & 7;
    const uint32_t arowb = (uint32_t)(wid * 16 + ((lane >> 3) & 1) * 8 + rn) * 128
                         + (uint32_t)((lane >> 4) * 8) * 2;
    const uint32_t brow0 = (uint32_t)((0 + (lane >> 4)) * 8 + rn) * 128
                         + (uint32_t)(((lane >> 3) & 1) * 8) * 2;
    const uint32_t brow2 = brow0 + 2 * 8 * 128;
    for (int kh = 0; kh < nkh; ++kh) {
        const uint32_t saKH = sa + kh * 16384;
        const uint32_t w0t = w0k + kh * WTILE_B;
        const uint32_t w1t = w1k + kh * WTILE_B;
        #pragma unroll
        for (int ks = 0; ks < 4; ++ks) {
            uint32_t a[4];
            ldm4(a, saKH + swz(arowb + ks * 32));
            if (d0) {
                uint32_t b[4], c[4];
                ldm4(b, w0t + swz(brow0 + ks * 32));
                ldm4(c, w0t + swz(brow2 + ks * 32));
                mma16816(a0[0], a, b + 0); mma16816(a0[1], a, b + 2);
                mma16816(a0[2], a, c + 0); mma16816(a0[3], a, c + 2);
            }
            if (d1) {
                uint32_t b[4], c[4];
                ldm4(b, w1t + swz(brow0 + ks * 32));
                ldm4(c, w1t + swz(brow2 + ks * 32));
                mma16816(a1[0], a, b + 0); mma16816(a1[1], a, b + 2);
                mma16816(a1[2], a, c + 0); mma16816(a1[3], a, c + 2);
            }
        }
    }
}

// Shuffle-free cell update: nt 0..3 = i,f,g,o for the same (row, unit) pairs.
__device__ __forceinline__ void cell_update(
    float acc[4][4], float cst[4], char* gdst, float* hlast,
    int ngrp, int mh, int wid, int lane)
{
    const int q   = lane & 3;
    const int hid = ngrp * 8 + 2 * q;
    const int kc  = hid >> 7, kh = (hid >> 6) & 1, kel = hid & 63;
    char* tile = gdst + ((size_t)((mh * 4 + kc) * 2 + kh)) * 16384;
    #pragma unroll
    for (int rh = 0; rh < 2; ++rh) {
        float hv[2];
        #pragma unroll
        for (int e = 0; e < 2; ++e) {
            const int d = rh * 2 + e;
            float ig = sigf(acc[0][d]);
            float fg = sigf(acc[1][d]);
            float gg = tanhfast(acc[2][d]);
            float og = sigf(acc[3][d]);
            float cc = fmaf(fg, cst[d], ig * gg);
            cst[d] = cc;
            hv[e] = og * tanhfast(cc);
        }
        const int row = wid * 16 + (lane >> 2) + rh * 8;
        __half2 h2 = __floats2half2_rn(hv[0], hv[1]);
        stg32(tile + swz((uint32_t)row * 128 + kel * 2), *(uint32_t*)&h2);
        if (hlast) {
            const int b = mh * 128 + row;
            stgf(hlast + (size_t)b * 512 + hid,     hv[0]);
            stgf(hlast + (size_t)b * 512 + hid + 1, hv[1]);
        }
    }
}

// ---------------------------------------------------------------------------
__global__ void __launch_bounds__(THREADS, 1) __cluster_dims__(2, 1, 1)
lstm_mma_kernel(
    const float* __restrict__ x,
    const float* __restrict__ Wih0, const float* __restrict__ Whh0,
    const float* __restrict__ bi0,  const float* __restrict__ bh0,
    const float* __restrict__ Wih1, const float* __restrict__ Whh1,
    const float* __restrict__ bi1,  const float* __restrict__ bh1,
    const float* __restrict__ Wfc1, const float* __restrict__ bfc1,
    const float* __restrict__ Wfc2, const float* __restrict__ bfc2,
    float* __restrict__ out)
{
    extern __shared__ char smem[];
    const uint32_t sbase = smem_u32(smem);
    const uint32_t FULL  = sbase;            // 3 x 8B
    const uint32_t EMPTY = sbase + 64;       // 3 x 8B
    const uint32_t WSB   = sbase + WS_OFF;
    const uint32_t HSB   = sbase + HS_OFF;

    const int tid  = threadIdx.x;
    const int lane = tid & 31;
    const int wid  = tid >> 5;
    const int c    = blockIdx.x;
    const int rank = c & 1;                  // cluster CTA rank
    const int mh   = (c >> 1) & 1;           // batch half (rows mh*128..)
    const int ngrp = ((c >> 2) << 1) | rank; // hidden-unit group (8 units)

    if (tid == 0) {
        #pragma unroll
        for (int s = 0; s < NSTAGE; ++s) {
            mbar_init(FULL + s * 8, 1);
            mbar_init(EMPTY + s * 8, 16);    // 8 warps x 2 CTAs
        }
    }
    __syncthreads();
    asm volatile("barrier.cluster.arrive.aligned;" ::: "memory");
    asm volatile("barrier.cluster.wait.aligned;" ::: "memory");

    uint32_t rEMPTY;
    asm("mapa.shared::cluster.u32 %0, %1, %2;"
        : "=r"(rEMPTY) : "r"(EMPTY), "r"(rank ^ 1));

    // ---- weights -> 25 resident fp16 SW128 tiles [32 gate cols x 64 k] ----
    for (int idx = tid; idx < 800; idx += THREADS) {
        const int ch = idx >> 5, rowi = idx & 31;
        const float* Wsrc; int ld, k0;
        if (ch == 0)      { Wsrc = Wih0; ld = 64;  k0 = 0; }
        else if (ch < 9)  { Wsrc = Whh0; ld = 512; k0 = (ch - 1) * 64; }
        else if (ch < 17) { Wsrc = Wih1; ld = 512; k0 = (ch - 9) * 64; }
        else              { Wsrc = Whh1; ld = 512; k0 = (ch - 17) * 64; }
        const int g = rowi >> 3, j = rowi & 7;
        const float* src = Wsrc + (size_t)(g * 512 + ngrp * 8 + j) * ld + k0;
        char* tb = smem + WS_OFF + ch * WTILE_B;
        for (int k = 0; k < 64; k += 2)
            *(__half2*)(tb + swz((uint32_t)rowi * 128 + k * 2)) =
                __floats2half2_rn(src[k], src[k + 1]);
    }

    // ---- biases: nt = gate, cols = units 2q,2q+1 ----
    const int q = lane & 3;
    float bias0[4][2], bias1[4][2];
    #pragma unroll
    for (int nt = 0; nt < 4; ++nt)
        #pragma unroll
        for (int e = 0; e < 2; ++e) {
            const int gc = nt * 512 + ngrp * 8 + 2 * q + e;
            bias0[nt][e] = bi0[gc] + bh0[gc];
            bias1[nt][e] = bi1[gc] + bh1[gc];
        }

    // ---- x -> fp16 swizzled 16KB tiles [t][mh2]; 8 tiles per CTA ----
    for (int w = 0; w < 8; ++w) {
        const int ti = c * 8 + w;
        const int t = ti >> 1, mh2 = ti & 1;
        char* dst = (char*)g_x16 + (size_t)ti * 16384;
        for (int p = 0; p < 16; ++p) {
            const int elem = tid + p * THREADS;       // 0..4095
            const int row = elem >> 5, kp = elem & 31;
            const float2 v = *(const float2*)(
                x + ((size_t)(mh2 * 128 + row) * 512 + t) * 64 + kp * 2);
            *(__half2*)(dst + swz((uint32_t)row * 128 + kp * 4)) =
                __floats2half2_rn(v.x, v.y);
        }
    }
    asm volatile("fence.proxy.async.global;" ::: "memory");
    grid_barrier();

    float cst0[4] = {}, cst1[4] = {};
    unsigned cons = 0;
    uint32_t st_ = 0, sa_ = 0;

    for (int t = 0; t <= 512; ++t) {
        const bool doL0  = (t < 512);
        const bool rec0  = doL0 && (t > 0);
        const bool doL1  = (t >= 1);
        const bool rec1  = (t >= 2);
        const bool h0grp = rec0 || doL1;

        // chunk list (in consumption order)
        const char* srcs[9];
        int nch = 0;
        if (doL0) srcs[nch++] = (const char*)g_x16 + ((size_t)t * 2 + mh) * 16384;
        if (h0grp) {
            const char* b = (const char*)g_h0[(t - 1) & 1] + (size_t)mh * 4 * 32768;
            for (int kc = 0; kc < 4; ++kc) srcs[nch++] = b + (size_t)kc * 32768;
        }
        if (rec1) {
            const char* b = (const char*)g_h1[t & 1] + (size_t)mh * 4 * 32768;
            for (int kc = 0; kc < 4; ++kc) srcs[nch++] = b + (size_t)kc * 32768;
        }

        const unsigned gc0 = cons;
        int pi = nch < NSTAGE ? nch : NSTAGE;
        if (tid == 0)
            for (int i2 = 0; i2 < pi; ++i2)
                issue_one(FULL, EMPTY, HSB, gc0 + i2, srcs[i2],
                          (doL0 && i2 == 0) ? 16384u : 32768u, rank);

        float acc0[4][4], acc1[4][4];
        #pragma unroll
        for (int nt = 0; nt < 4; ++nt) {
            acc0[nt][0] = bias0[nt][0]; acc0[nt][1] = bias0[nt][1];
            acc0[nt][2] = bias0[nt][0]; acc0[nt][3] = bias0[nt][1];
            acc1[nt][0] = bias1[nt][0]; acc1[nt][1] = bias1[nt][1];
            acc1[nt][2] = bias1[nt][0]; acc1[nt][3] = bias1[nt][1];
        }

        #define CPRE()                                                   \
            do { st_ = cons % 3u;                                        \
                 mbar_wait(FULL + st_ * 8, (cons / 3u) & 1u);            \
                 sa_ = HSB + st_ * STAGE_B; } while (0)
        #define CPOST()                                                  \
            do { if (lane == 0) {                                        \
                     mbar_arrive(EMPTY + st_ * 8);                       \
                     mbar_arrive_remote(rEMPTY + st_ * 8); }             \
                 ++cons;                                                 \
                 if (pi < nch) {                                         \
                     if (tid == 0)                                       \
                         issue_one(FULL, EMPTY, HSB, gc0 + pi,           \
                                   srcs[pi], 32768u, rank);              \
                     ++pi; } } while (0)

        if (doL0) {
            CPRE();
            gemm_chunk(acc0, acc1, sa_, WSB, WSB, true, false, 1, wid, lane);
            CPOST();
        }
        if (h0grp) {
            for (int kc = 0; kc < 4; ++kc) {
                CPRE();
                gemm_chunk(acc0, acc1, sa_,
                           WSB + (1 + kc * 2) * WTILE_B,
                           WSB + (9 + kc * 2) * WTILE_B,
                           rec0, doL1, 2, wid, lane);
                CPOST();
            }
        }
        if (doL0)
            cell_update(acc0, cst0, (char*)g_h0[t & 1], nullptr,
                        ngrp, mh, wid, lane);
        if (rec1) {
            for (int kc = 0; kc < 4; ++kc) {
                CPRE();
                gemm_chunk(acc1, acc0, sa_,
                           WSB + (17 + kc * 2) * WTILE_B, WSB,
                           true, false, 2, wid, lane);
                CPOST();
            }
        }
        if (doL1)
            cell_update(acc1, cst1, (char*)g_h1[(t - 1) & 1],
                        (t == 512) ? g_hlast : nullptr, ngrp, mh, wid, lane);

        asm volatile("fence.proxy.async.global;" ::: "memory");
        grid_barrier();
    }

    // ---------------- FC head: batch rows [2*c, 2*c+2) ----------------
    float* sm  = (float*)smem;
    float* shA = sm;
    float* shZ = sm + 1024;
    const int r0 = 2 * c;
    for (int i = tid; i < 1024; i += THREADS) {
        int row = i >> 9, k = i & 511;
        shA[i] = __ldcg(g_hlast + (size_t)(r0 + row) * 512 + k);
    }
    __syncthreads();

    #pragma unroll
    for (int ii = 0; ii < 2; ++ii) {
        int cc = tid + THREADS * ii;
        float a0v = bfc1[cc];
        float a1v = a0v;
        const float4* wr  = (const float4*)(Wfc1 + (size_t)cc * 512);
        const float4* hv0 = (const float4*)shA;
        const float4* hv1 = (const float4*)(shA + 512);
        #pragma unroll 4
        for (int k4 = 0; k4 < 128; ++k4) {
            float4 w = wr[k4];
            float4 p = hv0[k4];
            float4 qv = hv1[k4];
            a0v = fmaf(w.x, p.x, a0v);  a0v = fmaf(w.y, p.y, a0v);
            a0v = fmaf(w.z, p.z, a0v);  a0v = fmaf(w.w, p.w, a0v);
            a1v = fmaf(w.x, qv.x, a1v); a1v = fmaf(w.y, qv.y, a1v);
            a1v = fmaf(w.z, qv.z, a1v); a1v = fmaf(w.w, qv.w, a1v);
        }
        shZ[cc]       = fmaxf(a0v, 0.f);
        shZ[512 + cc] = fmaxf(a1v, 0.f);
    }
    __syncthreads();

    #pragma unroll
    for (int row = 0; row < 2; ++row) {
        const float4* zz = (const float4*)(shZ + row * 512);
        const float4* wf = (const float4*)(Wfc2 + (size_t)wid * 512);
        float s = 0.f;
        #pragma unroll
        for (int k4 = lane; k4 < 128; k4 += 32) {
            float4 ww = wf[k4];
            float4 zv = zz[k4];
            s = fmaf(ww.x, zv.x, s); s = fmaf(ww.y, zv.y, s);
            s = fmaf(ww.z, zv.z, s); s = fmaf(ww.w, zv.w, s);
        }
        #pragma unroll
        for (int off = 16; off; off >>= 1) s += __shfl_xor_sync(0xFFFFFFFFu, s, off);
        if (lane == 0) out[(r0 + row) * 8 + wid] = s + bfc2[wid];
    }

    asm volatile("barrier.cluster.arrive.aligned;" ::: "memory");
    asm volatile("barrier.cluster.wait.aligned;" ::: "memory");
}

// ---------------------------------------------------------------------------
extern "C" void kernel_launch(void* const* d_in, const int* in_sizes, int n_in,
                              void* d_out, int out_size)
{
    const float* x    = (const float*)d_in[0];
    const float* Wih0 = (const float*)d_in[1];
    const float* Whh0 = (const float*)d_in[2];
    const float* bi0  = (const float*)d_in[3];
    const float* bh0  = (const float*)d_in[4];
    const float* Wih1 = (const float*)d_in[5];
    const float* Whh1 = (const float*)d_in[6];
    const float* bi1  = (const float*)d_in[7];
    const float* bh1  = (const float*)d_in[8];
    const float* Wfc1 = (const float*)d_in[9];
    const float* bfc1 = (const float*)d_in[10];
    const float* Wfc2 = (const float*)d_in[11];
    const float* bfc2 = (const float*)d_in[12];
    float* out = (float*)d_out;

    cudaFuncSetAttribute(lstm_mma_kernel,
                         cudaFuncAttributeMaxDynamicSharedMemorySize, SMEM_BYTES);
    lstm_mma_kernel<<<NB, THREADS, SMEM_BYTES>>>(
        x, Wih0, Whh0, bi0, bh0, Wih1, Whh1, bi1, bh1,
        Wfc1, bfc1, Wfc2, bfc2, out);
}